// round 1
// baseline (speedup 1.0000x reference)
#include <cuda_runtime.h>
#include <cuda_bf16.h>

// ---------------------------------------------------------------------------
// MS-SSIM loss, (16,3,512,512) fp32 inputs, 5 levels, 7x7 Gaussian window.
// Strategy: per level one fused kernel computes all five depthwise convs via
// separable two-pass shared-memory tiles and reduces cs/ssim sums per batch
// into fp64 accumulators. A tiny pool kernel builds the next pyramid level.
// ---------------------------------------------------------------------------

#define B      16
#define CH     3
#define NIMG   (B * CH)

#define TW 32   // output tile width
#define TH 16   // output tile height
#define IW 38   // input tile width  (TW + 6)
#define IH 22   // input tile height (TH + 6)
#define NTHREADS 256

// Gaussian window, sigma=1.5, ws=7, normalized (matches np.exp computation)
__constant__ float c_G[7] = {
    0.036632845f, 0.111280762f, 0.216745317f, 0.270682752f,
    0.216745317f, 0.111280762f, 0.036632845f
};

#define C1v 0.0001f   // (0.01)^2
#define C2v 0.0009f   // (0.03)^2

// fp64 accumulators: [level][batch]
__device__ double g_cs[5][B];
__device__ double g_ssim[5][B];

// Scratch pyramid buffers for levels 1..4 (x and y)
// sizes per image: 256^2, 128^2, 64^2, 32^2
#define OFF1 0
#define OFF2 (NIMG * 256 * 256)                 // 3145728
#define OFF3 (OFF2 + NIMG * 128 * 128)          // 3932160
#define OFF4 (OFF3 + NIMG * 64 * 64)            // 4128768
#define BUFTOT (OFF4 + NIMG * 32 * 32)          // 4177920
__device__ float g_bufx[BUFTOT];
__device__ float g_bufy[BUFTOT];

__global__ void zero_acc_kernel() {
    int t = threadIdx.x;
    double* cs = &g_cs[0][0];
    double* ss = &g_ssim[0][0];
    if (t < 5 * B)           cs[t] = 0.0;
    else if (t < 10 * B)     ss[t - 5 * B] = 0.0;
}

// One block = one TH x TW output tile of one (b,c) image at one level.
__global__ __launch_bounds__(NTHREADS)
void ssim_kernel(const float* __restrict__ x, const float* __restrict__ y,
                 int W, int OW, int level) {
    __shared__ float sx[IH][IW + 2];
    __shared__ float sy[IH][IW + 2];
    __shared__ float h[5][IH][TW];   // horizontal-pass stats; reused for reduce

    const int img = blockIdx.z;                // b*CH + c
    const int b   = img / CH;
    const float* xp = x + (size_t)img * W * W;
    const float* yp = y + (size_t)img * W * W;

    const int ox0 = blockIdx.x * TW;
    const int oy0 = blockIdx.y * TH;
    const int tid = threadIdx.x;

    // ---- Phase 1: load (IH x IW) input window for x and y ----
    for (int e = tid; e < IH * IW; e += NTHREADS) {
        int r = e / IW, c = e - r * IW;
        int gy = oy0 + r, gx = ox0 + c;
        float xv = 0.f, yv = 0.f;
        if (gy < W && gx < W) {
            xv = xp[(size_t)gy * W + gx];
            yv = yp[(size_t)gy * W + gx];
        }
        sx[r][c] = xv;
        sy[r][c] = yv;
    }
    __syncthreads();

    // ---- Phase 2: horizontal Gaussian pass over 5 stats ----
    for (int e = tid; e < IH * TW; e += NTHREADS) {
        int r = e / TW, c = e - r * TW;
        float a0 = 0.f, a1 = 0.f, a2 = 0.f, a3 = 0.f, a4 = 0.f;
#pragma unroll
        for (int k = 0; k < 7; k++) {
            float w  = c_G[k];
            float xv = sx[r][c + k];
            float yv = sy[r][c + k];
            a0 += w * xv;
            a1 += w * yv;
            a2 += w * xv * xv;
            a3 += w * yv * yv;
            a4 += w * xv * yv;
        }
        h[0][r][c] = a0;
        h[1][r][c] = a1;
        h[2][r][c] = a2;
        h[3][r][c] = a3;
        h[4][r][c] = a4;
    }
    __syncthreads();

    // ---- Phase 3: vertical pass + SSIM math + local accumulate ----
    float cs_acc = 0.f, ssim_acc = 0.f;
    for (int e = tid; e < TH * TW; e += NTHREADS) {
        int i = e / TW, j = e - i * TW;
        int go_y = oy0 + i, go_x = ox0 + j;
        if (go_y < OW && go_x < OW) {
            float mu1 = 0.f, mu2 = 0.f, sxx = 0.f, syy = 0.f, sxy = 0.f;
#pragma unroll
            for (int k = 0; k < 7; k++) {
                float w = c_G[k];
                mu1 += w * h[0][i + k][j];
                mu2 += w * h[1][i + k][j];
                sxx += w * h[2][i + k][j];
                syy += w * h[3][i + k][j];
                sxy += w * h[4][i + k][j];
            }
            float mu1s = mu1 * mu1;
            float mu2s = mu2 * mu2;
            float mu12 = mu1 * mu2;
            float s1  = sxx - mu1s;
            float s2  = syy - mu2s;
            float s12 = sxy - mu12;
            float v1 = 2.f * s12 + C2v;
            float v2 = s1 + s2 + C2v;
            float cs = v1 / v2;
            float ssim = ((2.f * mu12 + C1v) * v1) / ((mu1s + mu2s + C1v) * v2);
            cs_acc   += cs;
            ssim_acc += ssim;
        }
    }

    // ---- Block reduction (reuse h memory) ----
    __syncthreads();
    float* red = &h[0][0][0];   // needs 2*NTHREADS floats; h has 3520
    red[tid]            = cs_acc;
    red[NTHREADS + tid] = ssim_acc;
    __syncthreads();
#pragma unroll
    for (int s = NTHREADS / 2; s > 0; s >>= 1) {
        if (tid < s) {
            red[tid]            += red[tid + s];
            red[NTHREADS + tid] += red[NTHREADS + tid + s];
        }
        __syncthreads();
    }
    if (tid == 0) {
        atomicAdd(&g_cs[level][b],   (double)red[0]);
        atomicAdd(&g_ssim[level][b], (double)red[NTHREADS]);
    }
}

// 2x2 average pool, both tensors in one launch (blockIdx.y selects x/y)
__global__ void pool_kernel(const float* __restrict__ srcx,
                            const float* __restrict__ srcy,
                            float* __restrict__ dstx,
                            float* __restrict__ dsty,
                            int W, int n) {
    int idx = blockIdx.x * blockDim.x + threadIdx.x;
    if (idx >= n) return;
    const float* src = blockIdx.y ? srcy : srcx;
    float*       dst = blockIdx.y ? dsty : dstx;
    int OW = W >> 1;
    int j   = idx % OW;
    int t   = idx / OW;
    int i   = t % OW;
    int img = t / OW;
    const float* p = src + ((size_t)img * W + 2 * i) * W + 2 * j;
    dst[idx] = 0.25f * (p[0] + p[1] + p[W] + p[W + 1]);
}

__global__ void final_kernel(float* out) {
    if (threadIdx.x != 0 || blockIdx.x != 0) return;
    const double wts[5] = {0.0448, 0.2856, 0.3001, 0.2363, 0.1333};
    const double cnt0 = (double)CH * 506 * 506;
    const double cnt1 = (double)CH * 250 * 250;
    const double cnt2 = (double)CH * 122 * 122;
    const double cnt3 = (double)CH * 58  * 58;
    const double cnt4 = (double)CH * 26  * 26;
    double total = 0.0;
    for (int b = 0; b < B; b++) {
        double vals[5];
        vals[0] = g_ssim[4][b] / cnt4;   // ssim of last level
        vals[1] = g_cs[0][b]   / cnt0;
        vals[2] = g_cs[1][b]   / cnt1;
        vals[3] = g_cs[2][b]   / cnt2;
        vals[4] = g_cs[3][b]   / cnt3;
        double m = 1.0;
        for (int l = 0; l < 5; l++) {
            double v = vals[l] < 1e-6 ? 1e-6 : vals[l];
            m *= pow(v, wts[l]);
        }
        total += m;
    }
    out[0] = (float)(1.0 - total / (double)B);
}

static inline void launch_ssim(const float* x, const float* y, int W, int level) {
    int OW = W - 6;
    dim3 grid((OW + TW - 1) / TW, (OW + TH - 1) / TH, NIMG);
    ssim_kernel<<<grid, NTHREADS>>>(x, y, W, OW, level);
}

static inline void launch_pool(const float* sx, const float* sy,
                               float* dx, float* dy, int W) {
    int OW = W >> 1;
    int n = NIMG * OW * OW;
    dim3 grid((n + 255) / 256, 2);
    pool_kernel<<<grid, 256>>>(sx, sy, dx, dy, W, n);
}

extern "C" void kernel_launch(void* const* d_in, const int* in_sizes, int n_in,
                              void* d_out, int out_size) {
    const float* x0 = (const float*)d_in[0];
    const float* y0 = (const float*)d_in[1];
    float* out = (float*)d_out;

    float *bx, *by;
    cudaGetSymbolAddress((void**)&bx, g_bufx);
    cudaGetSymbolAddress((void**)&by, g_bufy);

    float* x1 = bx + OFF1; float* y1 = by + OFF1;
    float* x2 = bx + OFF2; float* y2 = by + OFF2;
    float* x3 = bx + OFF3; float* y3 = by + OFF3;
    float* x4 = bx + OFF4; float* y4 = by + OFF4;

    zero_acc_kernel<<<1, 256>>>();

    launch_ssim(x0, y0, 512, 0);
    launch_pool(x0, y0, x1, y1, 512);

    launch_ssim(x1, y1, 256, 1);
    launch_pool(x1, y1, x2, y2, 256);

    launch_ssim(x2, y2, 128, 2);
    launch_pool(x2, y2, x3, y3, 128);

    launch_ssim(x3, y3, 64, 3);
    launch_pool(x3, y3, x4, y4, 64);

    launch_ssim(x4, y4, 32, 4);

    final_kernel<<<1, 32>>>(out);
}

// round 2
// speedup vs baseline: 1.4633x; 1.4633x over previous
#include <cuda_runtime.h>
#include <cuda_bf16.h>

// ---------------------------------------------------------------------------
// MS-SSIM loss, (16,3,512,512) fp32, 5 levels, 7x7 Gaussian.
// R2: register-blocked separable conv (4 outputs/thread both passes),
// fused 2x2 avg-pool (pool kernels eliminated), shuffle reduction,
// fast divides. Issue-bound optimization per R1 ncu (L1 74.7%, DRAM 6.7%).
// ---------------------------------------------------------------------------

#define B      16
#define CH     3
#define NIMG   (B * CH)

#define TW 32        // output tile width
#define TH 32        // output tile height
#define IW 38        // input tile width  (TW + 6)
#define IH 38        // input tile height (TH + 6)
#define SXP 39       // sx/sy padded row stride (odd -> conflict-free)
#define HP  33       // h padded row stride
#define NTHREADS 256

__constant__ float c_G[7] = {
    0.036632845f, 0.111280762f, 0.216745317f, 0.270682752f,
    0.216745317f, 0.111280762f, 0.036632845f
};

#define C1v 0.0001f
#define C2v 0.0009f

__device__ double g_cs[5][B];
__device__ double g_ssim[5][B];

// Pyramid scratch (levels 1..4), x and y
#define OFF1 0
#define OFF2 (NIMG * 256 * 256)
#define OFF3 (OFF2 + NIMG * 128 * 128)
#define OFF4 (OFF3 + NIMG * 64 * 64)
#define BUFTOT (OFF4 + NIMG * 32 * 32)
__device__ float g_bufx[BUFTOT];
__device__ float g_bufy[BUFTOT];

__global__ void zero_acc_kernel() {
    int t = threadIdx.x;
    double* cs = &g_cs[0][0];
    double* ss = &g_ssim[0][0];
    if (t < 5 * B)        cs[t] = 0.0;
    else if (t < 10 * B)  ss[t - 5 * B] = 0.0;
}

// One block = 32x32 output tile of one (b,c) image.
// Also writes the 16x16 pooled patch of its 32x32 core input region.
__global__ __launch_bounds__(NTHREADS)
void ssim_kernel(const float* __restrict__ x, const float* __restrict__ y,
                 float* __restrict__ poolx, float* __restrict__ pooly,
                 int W, int OW, int level, int do_pool) {
    __shared__ float sx[IH][SXP];
    __shared__ float sy[IH][SXP];
    __shared__ float h[5][IH][HP];
    __shared__ float red_cs[8], red_ss[8];

    const int img = blockIdx.z;
    const int b   = img / CH;
    const float* xp = x + (size_t)img * W * W;
    const float* yp = y + (size_t)img * W * W;

    const int ox0 = blockIdx.x * TW;
    const int oy0 = blockIdx.y * TH;
    const int tid = threadIdx.x;

    // ---- Phase 1: load (IH x IW) window, zero-filled beyond image ----
    for (int e = tid; e < IH * IW; e += NTHREADS) {
        int r = e / IW, c = e - r * IW;
        int gy = oy0 + r, gx = ox0 + c;
        float xv = 0.f, yv = 0.f;
        if (gy < W && gx < W) {
            xv = __ldg(&xp[(size_t)gy * W + gx]);
            yv = __ldg(&yp[(size_t)gy * W + gx]);
        }
        sx[r][c] = xv;
        sy[r][c] = yv;
    }
    __syncthreads();

    // ---- Fused 2x2 pool of the 32x32 core region ----
    if (do_pool) {
        int pi = tid >> 4, pj = tid & 15;       // 16x16 pooled outputs
        int r = 2 * pi, c = 2 * pj;
        float pvx = 0.25f * (sx[r][c] + sx[r][c+1] + sx[r+1][c] + sx[r+1][c+1]);
        float pvy = 0.25f * (sy[r][c] + sy[r][c+1] + sy[r+1][c] + sy[r+1][c+1]);
        int OW2 = W >> 1;
        size_t di = (size_t)img * OW2 * OW2 + ((oy0 >> 1) + pi) * OW2 + (ox0 >> 1) + pj;
        poolx[di] = pvx;
        pooly[di] = pvy;
    }

    // ---- Phase 2: horizontal Gaussian, 4 consecutive cols per task ----
    // tasks: IH rows x 8 col-groups = 304
    for (int t = tid; t < IH * 8; t += NTHREADS) {
        int r = t >> 3;
        int c0 = (t & 7) << 2;
        float xw[10], yw[10];
#pragma unroll
        for (int m = 0; m < 10; m++) {
            xw[m] = sx[r][c0 + m];
            yw[m] = sy[r][c0 + m];
        }
        float a0[4] = {0,0,0,0}, a1[4] = {0,0,0,0}, a2[4] = {0,0,0,0};
        float a3[4] = {0,0,0,0}, a4[4] = {0,0,0,0};
#pragma unroll
        for (int k = 0; k < 7; k++) {
            float w = c_G[k];
#pragma unroll
            for (int o = 0; o < 4; o++) {
                float xv = xw[k + o], yv = yw[k + o];
                float wx = w * xv, wy = w * yv;
                a0[o] += wx;
                a1[o] += wy;
                a2[o] = fmaf(wx, xv, a2[o]);
                a3[o] = fmaf(wy, yv, a3[o]);
                a4[o] = fmaf(wx, yv, a4[o]);
            }
        }
#pragma unroll
        for (int o = 0; o < 4; o++) {
            h[0][r][c0 + o] = a0[o];
            h[1][r][c0 + o] = a1[o];
            h[2][r][c0 + o] = a2[o];
            h[3][r][c0 + o] = a3[o];
            h[4][r][c0 + o] = a4[o];
        }
    }
    __syncthreads();

    // ---- Phase 3: vertical Gaussian, 4 consecutive rows per thread ----
    float cs_acc = 0.f, ssim_acc = 0.f;
    {
        int j  = tid & 31;
        int i0 = (tid >> 5) << 2;
        float m1[4] = {0,0,0,0}, m2[4] = {0,0,0,0};
        float s11[4] = {0,0,0,0}, s22[4] = {0,0,0,0}, s12[4] = {0,0,0,0};
#pragma unroll
        for (int k = 0; k < 10; k++) {
            float h0 = h[0][i0 + k][j];
            float h1 = h[1][i0 + k][j];
            float h2 = h[2][i0 + k][j];
            float h3 = h[3][i0 + k][j];
            float h4 = h[4][i0 + k][j];
#pragma unroll
            for (int o = 0; o < 4; o++) {
                int kk = k - o;
                if (kk >= 0 && kk < 7) {
                    float w = c_G[kk];
                    m1[o]  = fmaf(w, h0, m1[o]);
                    m2[o]  = fmaf(w, h1, m2[o]);
                    s11[o] = fmaf(w, h2, s11[o]);
                    s22[o] = fmaf(w, h3, s22[o]);
                    s12[o] = fmaf(w, h4, s12[o]);
                }
            }
        }
        bool colok = (ox0 + j) < OW;
#pragma unroll
        for (int o = 0; o < 4; o++) {
            if (colok && (oy0 + i0 + o) < OW) {
                float mu1 = m1[o], mu2 = m2[o];
                float mu1s = mu1 * mu1;
                float mu2s = mu2 * mu2;
                float mu12 = mu1 * mu2;
                float v1 = 2.f * (s12[o] - mu12) + C2v;
                float v2 = (s11[o] - mu1s) + (s22[o] - mu2s) + C2v;
                float cs = __fdividef(v1, v2);
                float ss = __fdividef((2.f * mu12 + C1v) * v1,
                                      (mu1s + mu2s + C1v) * v2);
                cs_acc   += cs;
                ssim_acc += ss;
            }
        }
    }

    // ---- Reduction: warp shuffle -> 8 partials -> 1 fp64 atomic each ----
#pragma unroll
    for (int s = 16; s > 0; s >>= 1) {
        cs_acc   += __shfl_xor_sync(0xffffffff, cs_acc, s);
        ssim_acc += __shfl_xor_sync(0xffffffff, ssim_acc, s);
    }
    int warp = tid >> 5, lane = tid & 31;
    if (lane == 0) { red_cs[warp] = cs_acc; red_ss[warp] = ssim_acc; }
    __syncthreads();
    if (tid == 0) {
        float tc = 0.f, ts = 0.f;
#pragma unroll
        for (int w = 0; w < 8; w++) { tc += red_cs[w]; ts += red_ss[w]; }
        atomicAdd(&g_cs[level][b],   (double)tc);
        atomicAdd(&g_ssim[level][b], (double)ts);
    }
}

__global__ void final_kernel(float* out) {
    if (threadIdx.x != 0 || blockIdx.x != 0) return;
    const double wts[5] = {0.0448, 0.2856, 0.3001, 0.2363, 0.1333};
    const double cnt[5] = {
        (double)CH * 506 * 506, (double)CH * 250 * 250,
        (double)CH * 122 * 122, (double)CH * 58 * 58, (double)CH * 26 * 26
    };
    double total = 0.0;
    for (int b = 0; b < B; b++) {
        double vals[5];
        vals[0] = g_ssim[4][b] / cnt[4];
        vals[1] = g_cs[0][b] / cnt[0];
        vals[2] = g_cs[1][b] / cnt[1];
        vals[3] = g_cs[2][b] / cnt[2];
        vals[4] = g_cs[3][b] / cnt[3];
        double m = 1.0;
        for (int l = 0; l < 5; l++) {
            double v = vals[l] < 1e-6 ? 1e-6 : vals[l];
            m *= pow(v, wts[l]);
        }
        total += m;
    }
    out[0] = (float)(1.0 - total / (double)B);
}

static inline void launch_ssim(const float* x, const float* y,
                               float* px, float* py, int W, int level) {
    int OW = W - 6;
    int nt = (OW + 31) / 32;
    dim3 grid(nt, nt, NIMG);
    ssim_kernel<<<grid, NTHREADS>>>(x, y, px, py, W, OW, level, px != nullptr);
}

extern "C" void kernel_launch(void* const* d_in, const int* in_sizes, int n_in,
                              void* d_out, int out_size) {
    const float* x0 = (const float*)d_in[0];
    const float* y0 = (const float*)d_in[1];
    float* out = (float*)d_out;

    float *bx, *by;
    cudaGetSymbolAddress((void**)&bx, g_bufx);
    cudaGetSymbolAddress((void**)&by, g_bufy);

    float* x1 = bx + OFF1; float* y1 = by + OFF1;
    float* x2 = bx + OFF2; float* y2 = by + OFF2;
    float* x3 = bx + OFF3; float* y3 = by + OFF3;
    float* x4 = bx + OFF4; float* y4 = by + OFF4;

    zero_acc_kernel<<<1, 256>>>();

    launch_ssim(x0, y0, x1, y1, 512, 0);
    launch_ssim(x1, y1, x2, y2, 256, 1);
    launch_ssim(x2, y2, x3, y3, 128, 2);
    launch_ssim(x3, y3, x4, y4,  64, 3);
    launch_ssim(x4, y4, nullptr, nullptr, 32, 4);

    final_kernel<<<1, 32>>>(out);
}

// round 3
// speedup vs baseline: 1.5279x; 1.0442x over previous
#include <cuda_runtime.h>
#include <cuda_bf16.h>

// ---------------------------------------------------------------------------
// MS-SSIM loss, (16,3,512,512) fp32, 5 levels, 7x7 Gaussian.
// R3: level-0 kernel builds the FULL pyramid (all 4 pooled levels) via
// shuffle/smem hierarchical pooling; levels 1-4 batched into one launch;
// float4 vectorized tile loads on interior fast path.
// ---------------------------------------------------------------------------

#define B      16
#define CH     3
#define NIMG   (B * CH)

#define TW 32
#define TH 32
#define IW 38
#define IH 38
#define SXP 39      // conflict-free padded stride for sx/sy
#define HP  33      // conflict-free padded stride for h
#define NTHREADS 256

__constant__ float c_G[7] = {
    0.036632845f, 0.111280762f, 0.216745317f, 0.270682752f,
    0.216745317f, 0.111280762f, 0.036632845f
};

#define C1v 0.0001f
#define C2v 0.0009f

__device__ double g_cs[5][B];
__device__ double g_ssim[5][B];

// Pyramid scratch (levels 1..4), x and y
#define OFF1 0
#define OFF2 (NIMG * 256 * 256)
#define OFF3 (OFF2 + NIMG * 128 * 128)
#define OFF4 (OFF3 + NIMG * 64 * 64)
#define BUFTOT (OFF4 + NIMG * 32 * 32)
__device__ float g_bufx[BUFTOT];
__device__ float g_bufy[BUFTOT];

__global__ void zero_acc_kernel() {
    int t = threadIdx.x;
    double* cs = &g_cs[0][0];
    double* ss = &g_ssim[0][0];
    if (t < 5 * B)        cs[t] = 0.0;
    else if (t < 10 * B)  ss[t - 5 * B] = 0.0;
}

// ---- shared phase 2+3+reduce body (sx/sy/h already in smem) --------------
__device__ __forceinline__ void ssim_core(
    float (*sx)[SXP], float (*sy)[SXP], float (*h)[IH][HP],
    float* red_cs, float* red_ss,
    int tid, int ox0, int oy0, int OW, int level, int b) {

    // Phase 2: horizontal Gaussian, 4 cols per task
    for (int t = tid; t < IH * 8; t += NTHREADS) {
        int r  = t >> 3;
        int c0 = (t & 7) << 2;
        float xw[10], yw[10];
#pragma unroll
        for (int m = 0; m < 10; m++) { xw[m] = sx[r][c0 + m]; yw[m] = sy[r][c0 + m]; }
        float a0[4] = {0,0,0,0}, a1[4] = {0,0,0,0}, a2[4] = {0,0,0,0};
        float a3[4] = {0,0,0,0}, a4[4] = {0,0,0,0};
#pragma unroll
        for (int k = 0; k < 7; k++) {
            float w = c_G[k];
#pragma unroll
            for (int o = 0; o < 4; o++) {
                float xv = xw[k + o], yv = yw[k + o];
                float wx = w * xv, wy = w * yv;
                a0[o] += wx;
                a1[o] += wy;
                a2[o] = fmaf(wx, xv, a2[o]);
                a3[o] = fmaf(wy, yv, a3[o]);
                a4[o] = fmaf(wx, yv, a4[o]);
            }
        }
#pragma unroll
        for (int o = 0; o < 4; o++) {
            h[0][r][c0 + o] = a0[o];
            h[1][r][c0 + o] = a1[o];
            h[2][r][c0 + o] = a2[o];
            h[3][r][c0 + o] = a3[o];
            h[4][r][c0 + o] = a4[o];
        }
    }
    __syncthreads();

    // Phase 3: vertical Gaussian, 4 rows per thread + SSIM math
    float cs_acc = 0.f, ssim_acc = 0.f;
    {
        int j  = tid & 31;
        int i0 = (tid >> 5) << 2;
        float m1[4] = {0,0,0,0}, m2[4] = {0,0,0,0};
        float s11[4] = {0,0,0,0}, s22[4] = {0,0,0,0}, s12[4] = {0,0,0,0};
#pragma unroll
        for (int k = 0; k < 10; k++) {
            float h0 = h[0][i0 + k][j];
            float h1 = h[1][i0 + k][j];
            float h2 = h[2][i0 + k][j];
            float h3 = h[3][i0 + k][j];
            float h4 = h[4][i0 + k][j];
#pragma unroll
            for (int o = 0; o < 4; o++) {
                int kk = k - o;
                if (kk >= 0 && kk < 7) {
                    float w = c_G[kk];
                    m1[o]  = fmaf(w, h0, m1[o]);
                    m2[o]  = fmaf(w, h1, m2[o]);
                    s11[o] = fmaf(w, h2, s11[o]);
                    s22[o] = fmaf(w, h3, s22[o]);
                    s12[o] = fmaf(w, h4, s12[o]);
                }
            }
        }
        bool colok = (ox0 + j) < OW;
#pragma unroll
        for (int o = 0; o < 4; o++) {
            if (colok && (oy0 + i0 + o) < OW) {
                float mu1 = m1[o], mu2 = m2[o];
                float mu1s = mu1 * mu1;
                float mu2s = mu2 * mu2;
                float mu12 = mu1 * mu2;
                float v1 = 2.f * (s12[o] - mu12) + C2v;
                float v2 = (s11[o] - mu1s) + (s22[o] - mu2s) + C2v;
                cs_acc   += __fdividef(v1, v2);
                ssim_acc += __fdividef((2.f * mu12 + C1v) * v1,
                                       (mu1s + mu2s + C1v) * v2);
            }
        }
    }

#pragma unroll
    for (int s = 16; s > 0; s >>= 1) {
        cs_acc   += __shfl_xor_sync(0xffffffff, cs_acc, s);
        ssim_acc += __shfl_xor_sync(0xffffffff, ssim_acc, s);
    }
    int warp = tid >> 5, lane = tid & 31;
    if (lane == 0) { red_cs[warp] = cs_acc; red_ss[warp] = ssim_acc; }
    __syncthreads();
    if (tid == 0) {
        float tc = 0.f, ts = 0.f;
#pragma unroll
        for (int w = 0; w < 8; w++) { tc += red_cs[w]; ts += red_ss[w]; }
        atomicAdd(&g_cs[level][b],   (double)tc);
        atomicAdd(&g_ssim[level][b], (double)ts);
    }
}

// ---- Level-0 kernel: ssim @512 + builds ALL pyramid levels ---------------
__global__ __launch_bounds__(NTHREADS)
void ssim0_kernel(const float* __restrict__ x, const float* __restrict__ y,
                  float* __restrict__ bx_, float* __restrict__ by_) {
    __shared__ float sx[IH][SXP];
    __shared__ float sy[IH][SXP];
    __shared__ float h[5][IH][HP];
    __shared__ float red_cs[8], red_ss[8];
    __shared__ float sp2x[64], sp2y[64], sp3x[16], sp3y[16];

    const int img = blockIdx.z;
    const int b   = img / CH;
    const float* xp = x + (size_t)img * 512 * 512;
    const float* yp = y + (size_t)img * 512 * 512;

    const int bxi = blockIdx.x, byi = blockIdx.y;
    const int ox0 = bxi * TW, oy0 = byi * TH;
    const int tid = threadIdx.x;

    // Phase 1: load 38x38 window
    if (bxi < 15 && byi < 15) {
        // interior fast path: 9x float4 + 1x float2 per row
        for (int t = tid; t < 380; t += NTHREADS) {
            int r = t / 10, v = t - r * 10;
            const float* rowx = xp + (size_t)(oy0 + r) * 512 + ox0;
            const float* rowy = yp + (size_t)(oy0 + r) * 512 + ox0;
            if (v < 9) {
                float4 a = __ldg((const float4*)rowx + v);
                float4 c = __ldg((const float4*)rowy + v);
                int cc = v << 2;
                sx[r][cc] = a.x; sx[r][cc+1] = a.y; sx[r][cc+2] = a.z; sx[r][cc+3] = a.w;
                sy[r][cc] = c.x; sy[r][cc+1] = c.y; sy[r][cc+2] = c.z; sy[r][cc+3] = c.w;
            } else {
                float2 a = __ldg((const float2*)(rowx + 36));
                float2 c = __ldg((const float2*)(rowy + 36));
                sx[r][36] = a.x; sx[r][37] = a.y;
                sy[r][36] = c.x; sy[r][37] = c.y;
            }
        }
    } else {
        for (int e = tid; e < IH * IW; e += NTHREADS) {
            int r = e / IW, c = e - r * IW;
            int gy = oy0 + r, gx = ox0 + c;
            float xv = 0.f, yv = 0.f;
            if (gy < 512 && gx < 512) {
                xv = __ldg(&xp[(size_t)gy * 512 + gx]);
                yv = __ldg(&yp[(size_t)gy * 512 + gx]);
            }
            sx[r][c] = xv;
            sy[r][c] = yv;
        }
    }
    __syncthreads();

    // Pyramid build from 32x32 core region (always fully in-bounds)
    {
        int pi = tid >> 4, pj = tid & 15;
        int r = 2 * pi, c = 2 * pj;
        float pvx = 0.25f * (sx[r][c] + sx[r][c+1] + sx[r+1][c] + sx[r+1][c+1]);
        float pvy = 0.25f * (sy[r][c] + sy[r][c+1] + sy[r+1][c] + sy[r+1][c+1]);
        // L1 (256x256)
        size_t d1 = (size_t)img * 256 * 256 + ((size_t)(oy0 >> 1) + pi) * 256 + (ox0 >> 1) + pj;
        bx_[OFF1 + d1] = pvx;
        by_[OFF1 + d1] = pvy;
        // L2 via warp butterfly (2x2 L1 block lives in one warp)
        int lane = tid & 31, wid = tid >> 5;
        float s2x = pvx + __shfl_xor_sync(0xffffffff, pvx, 1);
        s2x += __shfl_xor_sync(0xffffffff, s2x, 16);
        float s2y = pvy + __shfl_xor_sync(0xffffffff, pvy, 1);
        s2y += __shfl_xor_sync(0xffffffff, s2y, 16);
        if ((lane & 17) == 0) {
            float p2x = 0.25f * s2x, p2y = 0.25f * s2y;
            int i2 = wid, j2 = lane >> 1;
            size_t d2 = (size_t)img * 128 * 128 + ((size_t)(oy0 >> 2) + i2) * 128 + (ox0 >> 2) + j2;
            bx_[OFF2 + d2] = p2x;
            by_[OFF2 + d2] = p2y;
            sp2x[i2 * 8 + j2] = p2x;
            sp2y[i2 * 8 + j2] = p2y;
        }
    }
    __syncthreads();
    if (tid < 16) {
        int i3 = tid >> 2, j3 = tid & 3;
        int r = 2 * i3, c = 2 * j3;
        float p3x = 0.25f * (sp2x[r*8+c] + sp2x[r*8+c+1] + sp2x[(r+1)*8+c] + sp2x[(r+1)*8+c+1]);
        float p3y = 0.25f * (sp2y[r*8+c] + sp2y[r*8+c+1] + sp2y[(r+1)*8+c] + sp2y[(r+1)*8+c+1]);
        size_t d3 = (size_t)img * 64 * 64 + ((size_t)(oy0 >> 3) + i3) * 64 + (ox0 >> 3) + j3;
        bx_[OFF3 + d3] = p3x;
        by_[OFF3 + d3] = p3y;
        sp3x[tid] = p3x;
        sp3y[tid] = p3y;
    }
    __syncthreads();
    if (tid < 4) {
        int i4 = tid >> 1, j4 = tid & 1;
        int r = 2 * i4, c = 2 * j4;
        float p4x = 0.25f * (sp3x[r*4+c] + sp3x[r*4+c+1] + sp3x[(r+1)*4+c] + sp3x[(r+1)*4+c+1]);
        float p4y = 0.25f * (sp3y[r*4+c] + sp3y[r*4+c+1] + sp3y[(r+1)*4+c] + sp3y[(r+1)*4+c+1]);
        size_t d4 = (size_t)img * 32 * 32 + ((size_t)(oy0 >> 4) + i4) * 32 + (ox0 >> 4) + j4;
        bx_[OFF4 + d4] = p4x;
        by_[OFF4 + d4] = p4y;
    }
    // no extra sync needed: pool smem arrays are disjoint from h

    ssim_core(sx, sy, h, red_cs, red_ss, tid, ox0, oy0, 506, 0, b);
}

// ---- Batched levels 1..4 kernel ------------------------------------------
__global__ __launch_bounds__(NTHREADS)
void ssimL_kernel(const float* __restrict__ bx_, const float* __restrict__ by_) {
    const int z   = blockIdx.z;
    const int lvl = z / NIMG;          // 0..3 -> actual level 1..4
    const int img = z - lvl * NIMG;

    const int Wtab[4]  = {256, 128, 64, 32};
    const int nttab[4] = {8, 4, 2, 1};
    const size_t offtab[4] = {OFF1, OFF2, OFF3, OFF4};

    const int W  = Wtab[lvl];
    const int nt = nttab[lvl];
    if ((int)blockIdx.x >= nt || (int)blockIdx.y >= nt) return;

    __shared__ float sx[IH][SXP];
    __shared__ float sy[IH][SXP];
    __shared__ float h[5][IH][HP];
    __shared__ float red_cs[8], red_ss[8];

    const int b = img / CH;
    const float* xp = bx_ + offtab[lvl] + (size_t)img * W * W;
    const float* yp = by_ + offtab[lvl] + (size_t)img * W * W;

    const int ox0 = blockIdx.x * TW;
    const int oy0 = blockIdx.y * TH;
    const int tid = threadIdx.x;

    if (ox0 + IW <= W && oy0 + IW <= W) {
        for (int t = tid; t < 380; t += NTHREADS) {
            int r = t / 10, v = t - r * 10;
            const float* rowx = xp + (size_t)(oy0 + r) * W + ox0;
            const float* rowy = yp + (size_t)(oy0 + r) * W + ox0;
            if (v < 9) {
                float4 a = __ldg((const float4*)rowx + v);
                float4 c = __ldg((const float4*)rowy + v);
                int cc = v << 2;
                sx[r][cc] = a.x; sx[r][cc+1] = a.y; sx[r][cc+2] = a.z; sx[r][cc+3] = a.w;
                sy[r][cc] = c.x; sy[r][cc+1] = c.y; sy[r][cc+2] = c.z; sy[r][cc+3] = c.w;
            } else {
                float2 a = __ldg((const float2*)(rowx + 36));
                float2 c = __ldg((const float2*)(rowy + 36));
                sx[r][36] = a.x; sx[r][37] = a.y;
                sy[r][36] = c.x; sy[r][37] = c.y;
            }
        }
    } else {
        for (int e = tid; e < IH * IW; e += NTHREADS) {
            int r = e / IW, c = e - r * IW;
            int gy = oy0 + r, gx = ox0 + c;
            float xv = 0.f, yv = 0.f;
            if (gy < W && gx < W) {
                xv = __ldg(&xp[(size_t)gy * W + gx]);
                yv = __ldg(&yp[(size_t)gy * W + gx]);
            }
            sx[r][c] = xv;
            sy[r][c] = yv;
        }
    }
    __syncthreads();

    ssim_core(sx, sy, h, red_cs, red_ss, tid, ox0, oy0, W - 6, 1 + lvl, b);
}

__global__ void final_kernel(float* out) {
    if (threadIdx.x != 0 || blockIdx.x != 0) return;
    const double wts[5] = {0.0448, 0.2856, 0.3001, 0.2363, 0.1333};
    const double cnt[5] = {
        (double)CH * 506 * 506, (double)CH * 250 * 250,
        (double)CH * 122 * 122, (double)CH * 58 * 58, (double)CH * 26 * 26
    };
    double total = 0.0;
    for (int b = 0; b < B; b++) {
        double vals[5];
        vals[0] = g_ssim[4][b] / cnt[4];
        vals[1] = g_cs[0][b] / cnt[0];
        vals[2] = g_cs[1][b] / cnt[1];
        vals[3] = g_cs[2][b] / cnt[2];
        vals[4] = g_cs[3][b] / cnt[3];
        double m = 1.0;
        for (int l = 0; l < 5; l++) {
            double v = vals[l] < 1e-6 ? 1e-6 : vals[l];
            m *= pow(v, wts[l]);
        }
        total += m;
    }
    out[0] = (float)(1.0 - total / (double)B);
}

extern "C" void kernel_launch(void* const* d_in, const int* in_sizes, int n_in,
                              void* d_out, int out_size) {
    const float* x0 = (const float*)d_in[0];
    const float* y0 = (const float*)d_in[1];
    float* out = (float*)d_out;

    float *bx, *by;
    cudaGetSymbolAddress((void**)&bx, g_bufx);
    cudaGetSymbolAddress((void**)&by, g_bufy);

    zero_acc_kernel<<<1, 256>>>();

    dim3 g0(16, 16, NIMG);
    ssim0_kernel<<<g0, NTHREADS>>>(x0, y0, bx, by);

    dim3 gL(8, 8, 4 * NIMG);
    ssimL_kernel<<<gL, NTHREADS>>>(bx, by);

    final_kernel<<<1, 32>>>(out);
}

// round 4
// speedup vs baseline: 1.8357x; 1.2014x over previous
#include <cuda_runtime.h>
#include <cuda_bf16.h>

// ---------------------------------------------------------------------------
// MS-SSIM loss, (16,3,512,512) fp32, 5 levels, 7x7 Gaussian.
// R4: R3 structure (fused pyramid build in level-0 kernel, batched levels
// 1-4) + parallelized epilogue: the serial fp64 pow() final kernel (37.6us
// per ncu!) replaced by a 16-thread fp32 log/exp geometric mean (~1.5us).
// ---------------------------------------------------------------------------

#define B      16
#define CH     3
#define NIMG   (B * CH)

#define TW 32
#define TH 32
#define IW 38
#define IH 38
#define SXP 39      // conflict-free padded stride for sx/sy
#define HP  33      // conflict-free padded stride for h
#define NTHREADS 256

__constant__ float c_G[7] = {
    0.036632845f, 0.111280762f, 0.216745317f, 0.270682752f,
    0.216745317f, 0.111280762f, 0.036632845f
};

#define C1v 0.0001f
#define C2v 0.0009f

__device__ double g_cs[5][B];
__device__ double g_ssim[5][B];

// Pyramid scratch (levels 1..4), x and y
#define OFF1 0
#define OFF2 (NIMG * 256 * 256)
#define OFF3 (OFF2 + NIMG * 128 * 128)
#define OFF4 (OFF3 + NIMG * 64 * 64)
#define BUFTOT (OFF4 + NIMG * 32 * 32)
__device__ float g_bufx[BUFTOT];
__device__ float g_bufy[BUFTOT];

__global__ void zero_acc_kernel() {
    int t = threadIdx.x;
    double* cs = &g_cs[0][0];
    double* ss = &g_ssim[0][0];
    if (t < 5 * B)        cs[t] = 0.0;
    else if (t < 10 * B)  ss[t - 5 * B] = 0.0;
}

// ---- shared phase 2+3+reduce body (sx/sy/h already in smem) --------------
__device__ __forceinline__ void ssim_core(
    float (*sx)[SXP], float (*sy)[SXP], float (*h)[IH][HP],
    float* red_cs, float* red_ss,
    int tid, int ox0, int oy0, int OW, int level, int b) {

    // Phase 2: horizontal Gaussian, 4 cols per task
    for (int t = tid; t < IH * 8; t += NTHREADS) {
        int r  = t >> 3;
        int c0 = (t & 7) << 2;
        float xw[10], yw[10];
#pragma unroll
        for (int m = 0; m < 10; m++) { xw[m] = sx[r][c0 + m]; yw[m] = sy[r][c0 + m]; }
        float a0[4] = {0,0,0,0}, a1[4] = {0,0,0,0}, a2[4] = {0,0,0,0};
        float a3[4] = {0,0,0,0}, a4[4] = {0,0,0,0};
#pragma unroll
        for (int k = 0; k < 7; k++) {
            float w = c_G[k];
#pragma unroll
            for (int o = 0; o < 4; o++) {
                float xv = xw[k + o], yv = yw[k + o];
                float wx = w * xv, wy = w * yv;
                a0[o] += wx;
                a1[o] += wy;
                a2[o] = fmaf(wx, xv, a2[o]);
                a3[o] = fmaf(wy, yv, a3[o]);
                a4[o] = fmaf(wx, yv, a4[o]);
            }
        }
#pragma unroll
        for (int o = 0; o < 4; o++) {
            h[0][r][c0 + o] = a0[o];
            h[1][r][c0 + o] = a1[o];
            h[2][r][c0 + o] = a2[o];
            h[3][r][c0 + o] = a3[o];
            h[4][r][c0 + o] = a4[o];
        }
    }
    __syncthreads();

    // Phase 3: vertical Gaussian, 4 rows per thread + SSIM math
    float cs_acc = 0.f, ssim_acc = 0.f;
    {
        int j  = tid & 31;
        int i0 = (tid >> 5) << 2;
        float m1[4] = {0,0,0,0}, m2[4] = {0,0,0,0};
        float s11[4] = {0,0,0,0}, s22[4] = {0,0,0,0}, s12[4] = {0,0,0,0};
#pragma unroll
        for (int k = 0; k < 10; k++) {
            float h0 = h[0][i0 + k][j];
            float h1 = h[1][i0 + k][j];
            float h2 = h[2][i0 + k][j];
            float h3 = h[3][i0 + k][j];
            float h4 = h[4][i0 + k][j];
#pragma unroll
            for (int o = 0; o < 4; o++) {
                int kk = k - o;
                if (kk >= 0 && kk < 7) {
                    float w = c_G[kk];
                    m1[o]  = fmaf(w, h0, m1[o]);
                    m2[o]  = fmaf(w, h1, m2[o]);
                    s11[o] = fmaf(w, h2, s11[o]);
                    s22[o] = fmaf(w, h3, s22[o]);
                    s12[o] = fmaf(w, h4, s12[o]);
                }
            }
        }
        bool colok = (ox0 + j) < OW;
#pragma unroll
        for (int o = 0; o < 4; o++) {
            if (colok && (oy0 + i0 + o) < OW) {
                float mu1 = m1[o], mu2 = m2[o];
                float mu1s = mu1 * mu1;
                float mu2s = mu2 * mu2;
                float mu12 = mu1 * mu2;
                float v1 = 2.f * (s12[o] - mu12) + C2v;
                float v2 = (s11[o] - mu1s) + (s22[o] - mu2s) + C2v;
                cs_acc   += __fdividef(v1, v2);
                ssim_acc += __fdividef((2.f * mu12 + C1v) * v1,
                                       (mu1s + mu2s + C1v) * v2);
            }
        }
    }

#pragma unroll
    for (int s = 16; s > 0; s >>= 1) {
        cs_acc   += __shfl_xor_sync(0xffffffff, cs_acc, s);
        ssim_acc += __shfl_xor_sync(0xffffffff, ssim_acc, s);
    }
    int warp = tid >> 5, lane = tid & 31;
    if (lane == 0) { red_cs[warp] = cs_acc; red_ss[warp] = ssim_acc; }
    __syncthreads();
    if (tid == 0) {
        float tc = 0.f, ts = 0.f;
#pragma unroll
        for (int w = 0; w < 8; w++) { tc += red_cs[w]; ts += red_ss[w]; }
        atomicAdd(&g_cs[level][b],   (double)tc);
        atomicAdd(&g_ssim[level][b], (double)ts);
    }
}

// ---- Level-0 kernel: ssim @512 + builds ALL pyramid levels ---------------
__global__ __launch_bounds__(NTHREADS)
void ssim0_kernel(const float* __restrict__ x, const float* __restrict__ y,
                  float* __restrict__ bx_, float* __restrict__ by_) {
    __shared__ float sx[IH][SXP];
    __shared__ float sy[IH][SXP];
    __shared__ float h[5][IH][HP];
    __shared__ float red_cs[8], red_ss[8];
    __shared__ float sp2x[64], sp2y[64], sp3x[16], sp3y[16];

    const int img = blockIdx.z;
    const int b   = img / CH;
    const float* xp = x + (size_t)img * 512 * 512;
    const float* yp = y + (size_t)img * 512 * 512;

    const int bxi = blockIdx.x, byi = blockIdx.y;
    const int ox0 = bxi * TW, oy0 = byi * TH;
    const int tid = threadIdx.x;

    // Phase 1: load 38x38 window
    if (bxi < 15 && byi < 15) {
        for (int t = tid; t < 380; t += NTHREADS) {
            int r = t / 10, v = t - r * 10;
            const float* rowx = xp + (size_t)(oy0 + r) * 512 + ox0;
            const float* rowy = yp + (size_t)(oy0 + r) * 512 + ox0;
            if (v < 9) {
                float4 a = __ldg((const float4*)rowx + v);
                float4 c = __ldg((const float4*)rowy + v);
                int cc = v << 2;
                sx[r][cc] = a.x; sx[r][cc+1] = a.y; sx[r][cc+2] = a.z; sx[r][cc+3] = a.w;
                sy[r][cc] = c.x; sy[r][cc+1] = c.y; sy[r][cc+2] = c.z; sy[r][cc+3] = c.w;
            } else {
                float2 a = __ldg((const float2*)(rowx + 36));
                float2 c = __ldg((const float2*)(rowy + 36));
                sx[r][36] = a.x; sx[r][37] = a.y;
                sy[r][36] = c.x; sy[r][37] = c.y;
            }
        }
    } else {
        for (int e = tid; e < IH * IW; e += NTHREADS) {
            int r = e / IW, c = e - r * IW;
            int gy = oy0 + r, gx = ox0 + c;
            float xv = 0.f, yv = 0.f;
            if (gy < 512 && gx < 512) {
                xv = __ldg(&xp[(size_t)gy * 512 + gx]);
                yv = __ldg(&yp[(size_t)gy * 512 + gx]);
            }
            sx[r][c] = xv;
            sy[r][c] = yv;
        }
    }
    __syncthreads();

    // Pyramid build from 32x32 core region (always fully in-bounds)
    {
        int pi = tid >> 4, pj = tid & 15;
        int r = 2 * pi, c = 2 * pj;
        float pvx = 0.25f * (sx[r][c] + sx[r][c+1] + sx[r+1][c] + sx[r+1][c+1]);
        float pvy = 0.25f * (sy[r][c] + sy[r][c+1] + sy[r+1][c] + sy[r+1][c+1]);
        size_t d1 = (size_t)img * 256 * 256 + ((size_t)(oy0 >> 1) + pi) * 256 + (ox0 >> 1) + pj;
        bx_[OFF1 + d1] = pvx;
        by_[OFF1 + d1] = pvy;
        int lane = tid & 31, wid = tid >> 5;
        float s2x = pvx + __shfl_xor_sync(0xffffffff, pvx, 1);
        s2x += __shfl_xor_sync(0xffffffff, s2x, 16);
        float s2y = pvy + __shfl_xor_sync(0xffffffff, pvy, 1);
        s2y += __shfl_xor_sync(0xffffffff, s2y, 16);
        if ((lane & 17) == 0) {
            float p2x = 0.25f * s2x, p2y = 0.25f * s2y;
            int i2 = wid, j2 = lane >> 1;
            size_t d2 = (size_t)img * 128 * 128 + ((size_t)(oy0 >> 2) + i2) * 128 + (ox0 >> 2) + j2;
            bx_[OFF2 + d2] = p2x;
            by_[OFF2 + d2] = p2y;
            sp2x[i2 * 8 + j2] = p2x;
            sp2y[i2 * 8 + j2] = p2y;
        }
    }
    __syncthreads();
    if (tid < 16) {
        int i3 = tid >> 2, j3 = tid & 3;
        int r = 2 * i3, c = 2 * j3;
        float p3x = 0.25f * (sp2x[r*8+c] + sp2x[r*8+c+1] + sp2x[(r+1)*8+c] + sp2x[(r+1)*8+c+1]);
        float p3y = 0.25f * (sp2y[r*8+c] + sp2y[r*8+c+1] + sp2y[(r+1)*8+c] + sp2y[(r+1)*8+c+1]);
        size_t d3 = (size_t)img * 64 * 64 + ((size_t)(oy0 >> 3) + i3) * 64 + (ox0 >> 3) + j3;
        bx_[OFF3 + d3] = p3x;
        by_[OFF3 + d3] = p3y;
        sp3x[tid] = p3x;
        sp3y[tid] = p3y;
    }
    __syncthreads();
    if (tid < 4) {
        int i4 = tid >> 1, j4 = tid & 1;
        int r = 2 * i4, c = 2 * j4;
        float p4x = 0.25f * (sp3x[r*4+c] + sp3x[r*4+c+1] + sp3x[(r+1)*4+c] + sp3x[(r+1)*4+c+1]);
        float p4y = 0.25f * (sp3y[r*4+c] + sp3y[r*4+c+1] + sp3y[(r+1)*4+c] + sp3y[(r+1)*4+c+1]);
        size_t d4 = (size_t)img * 32 * 32 + ((size_t)(oy0 >> 4) + i4) * 32 + (ox0 >> 4) + j4;
        bx_[OFF4 + d4] = p4x;
        by_[OFF4 + d4] = p4y;
    }

    ssim_core(sx, sy, h, red_cs, red_ss, tid, ox0, oy0, 506, 0, b);
}

// ---- Batched levels 1..4 kernel ------------------------------------------
__global__ __launch_bounds__(NTHREADS)
void ssimL_kernel(const float* __restrict__ bx_, const float* __restrict__ by_) {
    const int z   = blockIdx.z;
    const int lvl = z / NIMG;          // 0..3 -> actual level 1..4
    const int img = z - lvl * NIMG;

    const int Wtab[4]  = {256, 128, 64, 32};
    const int nttab[4] = {8, 4, 2, 1};
    const size_t offtab[4] = {OFF1, OFF2, OFF3, OFF4};

    const int W  = Wtab[lvl];
    const int nt = nttab[lvl];
    if ((int)blockIdx.x >= nt || (int)blockIdx.y >= nt) return;

    __shared__ float sx[IH][SXP];
    __shared__ float sy[IH][SXP];
    __shared__ float h[5][IH][HP];
    __shared__ float red_cs[8], red_ss[8];

    const int b = img / CH;
    const float* xp = bx_ + offtab[lvl] + (size_t)img * W * W;
    const float* yp = by_ + offtab[lvl] + (size_t)img * W * W;

    const int ox0 = blockIdx.x * TW;
    const int oy0 = blockIdx.y * TH;
    const int tid = threadIdx.x;

    if (ox0 + IW <= W && oy0 + IW <= W) {
        for (int t = tid; t < 380; t += NTHREADS) {
            int r = t / 10, v = t - r * 10;
            const float* rowx = xp + (size_t)(oy0 + r) * W + ox0;
            const float* rowy = yp + (size_t)(oy0 + r) * W + ox0;
            if (v < 9) {
                float4 a = __ldg((const float4*)rowx + v);
                float4 c = __ldg((const float4*)rowy + v);
                int cc = v << 2;
                sx[r][cc] = a.x; sx[r][cc+1] = a.y; sx[r][cc+2] = a.z; sx[r][cc+3] = a.w;
                sy[r][cc] = c.x; sy[r][cc+1] = c.y; sy[r][cc+2] = c.z; sy[r][cc+3] = c.w;
            } else {
                float2 a = __ldg((const float2*)(rowx + 36));
                float2 c = __ldg((const float2*)(rowy + 36));
                sx[r][36] = a.x; sx[r][37] = a.y;
                sy[r][36] = c.x; sy[r][37] = c.y;
            }
        }
    } else {
        for (int e = tid; e < IH * IW; e += NTHREADS) {
            int r = e / IW, c = e - r * IW;
            int gy = oy0 + r, gx = ox0 + c;
            float xv = 0.f, yv = 0.f;
            if (gy < W && gx < W) {
                xv = __ldg(&xp[(size_t)gy * W + gx]);
                yv = __ldg(&yp[(size_t)gy * W + gx]);
            }
            sx[r][c] = xv;
            sy[r][c] = yv;
        }
    }
    __syncthreads();

    ssim_core(sx, sy, h, red_cs, red_ss, tid, ox0, oy0, W - 6, 1 + lvl, b);
}

// ---- Parallel epilogue: one warp, fp32 log/exp geometric mean ------------
__global__ void final_kernel(float* out) {
    const int t = threadIdx.x;
    float m = 0.f;
    if (t < B) {
        const float wts[5] = {0.0448f, 0.2856f, 0.3001f, 0.2363f, 0.1333f};
        const float inv_cnt[5] = {
            1.f / (CH * 506.f * 506.f), 1.f / (CH * 250.f * 250.f),
            1.f / (CH * 122.f * 122.f), 1.f / (CH * 58.f * 58.f),
            1.f / (CH * 26.f * 26.f)
        };
        float vals[5];
        vals[0] = (float)g_ssim[4][t] * inv_cnt[4];
        vals[1] = (float)g_cs[0][t]   * inv_cnt[0];
        vals[2] = (float)g_cs[1][t]   * inv_cnt[1];
        vals[3] = (float)g_cs[2][t]   * inv_cnt[2];
        vals[4] = (float)g_cs[3][t]   * inv_cnt[3];
        float lacc = 0.f;
#pragma unroll
        for (int l = 0; l < 5; l++) {
            float v = vals[l] < 1e-6f ? 1e-6f : vals[l];
            lacc = fmaf(wts[l], __logf(v), lacc);
        }
        m = __expf(lacc);
    }
#pragma unroll
    for (int s = 8; s > 0; s >>= 1)
        m += __shfl_xor_sync(0xffffffff, m, s);
    if (t == 0)
        out[0] = 1.f - m * (1.f / (float)B);
}

extern "C" void kernel_launch(void* const* d_in, const int* in_sizes, int n_in,
                              void* d_out, int out_size) {
    const float* x0 = (const float*)d_in[0];
    const float* y0 = (const float*)d_in[1];
    float* out = (float*)d_out;

    float *bx, *by;
    cudaGetSymbolAddress((void**)&bx, g_bufx);
    cudaGetSymbolAddress((void**)&by, g_bufy);

    zero_acc_kernel<<<1, 256>>>();

    dim3 g0(16, 16, NIMG);
    ssim0_kernel<<<g0, NTHREADS>>>(x0, y0, bx, by);

    dim3 gL(8, 8, 4 * NIMG);
    ssimL_kernel<<<gL, NTHREADS>>>(bx, by);

    final_kernel<<<1, 32>>>(out);
}

// round 5
// speedup vs baseline: 1.8360x; 1.0002x over previous
#include <cuda_runtime.h>
#include <cuda_bf16.h>

// ---------------------------------------------------------------------------
// MS-SSIM loss, (16,3,512,512) fp32, 5 levels, 7x7 Gaussian.
// R4: R3 structure (fused pyramid build in level-0 kernel, batched levels
// 1-4) + parallelized epilogue: the serial fp64 pow() final kernel (37.6us
// per ncu!) replaced by a 16-thread fp32 log/exp geometric mean (~1.5us).
// ---------------------------------------------------------------------------

#define B      16
#define CH     3
#define NIMG   (B * CH)

#define TW 32
#define TH 32
#define IW 38
#define IH 38
#define SXP 39      // conflict-free padded stride for sx/sy
#define HP  33      // conflict-free padded stride for h
#define NTHREADS 256

__constant__ float c_G[7] = {
    0.036632845f, 0.111280762f, 0.216745317f, 0.270682752f,
    0.216745317f, 0.111280762f, 0.036632845f
};

#define C1v 0.0001f
#define C2v 0.0009f

__device__ double g_cs[5][B];
__device__ double g_ssim[5][B];

// Pyramid scratch (levels 1..4), x and y
#define OFF1 0
#define OFF2 (NIMG * 256 * 256)
#define OFF3 (OFF2 + NIMG * 128 * 128)
#define OFF4 (OFF3 + NIMG * 64 * 64)
#define BUFTOT (OFF4 + NIMG * 32 * 32)
__device__ float g_bufx[BUFTOT];
__device__ float g_bufy[BUFTOT];

__global__ void zero_acc_kernel() {
    int t = threadIdx.x;
    double* cs = &g_cs[0][0];
    double* ss = &g_ssim[0][0];
    if (t < 5 * B)        cs[t] = 0.0;
    else if (t < 10 * B)  ss[t - 5 * B] = 0.0;
}

// ---- shared phase 2+3+reduce body (sx/sy/h already in smem) --------------
__device__ __forceinline__ void ssim_core(
    float (*sx)[SXP], float (*sy)[SXP], float (*h)[IH][HP],
    float* red_cs, float* red_ss,
    int tid, int ox0, int oy0, int OW, int level, int b) {

    // Phase 2: horizontal Gaussian, 4 cols per task
    for (int t = tid; t < IH * 8; t += NTHREADS) {
        int r  = t >> 3;
        int c0 = (t & 7) << 2;
        float xw[10], yw[10];
#pragma unroll
        for (int m = 0; m < 10; m++) { xw[m] = sx[r][c0 + m]; yw[m] = sy[r][c0 + m]; }
        float a0[4] = {0,0,0,0}, a1[4] = {0,0,0,0}, a2[4] = {0,0,0,0};
        float a3[4] = {0,0,0,0}, a4[4] = {0,0,0,0};
#pragma unroll
        for (int k = 0; k < 7; k++) {
            float w = c_G[k];
#pragma unroll
            for (int o = 0; o < 4; o++) {
                float xv = xw[k + o], yv = yw[k + o];
                float wx = w * xv, wy = w * yv;
                a0[o] += wx;
                a1[o] += wy;
                a2[o] = fmaf(wx, xv, a2[o]);
                a3[o] = fmaf(wy, yv, a3[o]);
                a4[o] = fmaf(wx, yv, a4[o]);
            }
        }
#pragma unroll
        for (int o = 0; o < 4; o++) {
            h[0][r][c0 + o] = a0[o];
            h[1][r][c0 + o] = a1[o];
            h[2][r][c0 + o] = a2[o];
            h[3][r][c0 + o] = a3[o];
            h[4][r][c0 + o] = a4[o];
        }
    }
    __syncthreads();

    // Phase 3: vertical Gaussian, 4 rows per thread + SSIM math
    float cs_acc = 0.f, ssim_acc = 0.f;
    {
        int j  = tid & 31;
        int i0 = (tid >> 5) << 2;
        float m1[4] = {0,0,0,0}, m2[4] = {0,0,0,0};
        float s11[4] = {0,0,0,0}, s22[4] = {0,0,0,0}, s12[4] = {0,0,0,0};
#pragma unroll
        for (int k = 0; k < 10; k++) {
            float h0 = h[0][i0 + k][j];
            float h1 = h[1][i0 + k][j];
            float h2 = h[2][i0 + k][j];
            float h3 = h[3][i0 + k][j];
            float h4 = h[4][i0 + k][j];
#pragma unroll
            for (int o = 0; o < 4; o++) {
                int kk = k - o;
                if (kk >= 0 && kk < 7) {
                    float w = c_G[kk];
                    m1[o]  = fmaf(w, h0, m1[o]);
                    m2[o]  = fmaf(w, h1, m2[o]);
                    s11[o] = fmaf(w, h2, s11[o]);
                    s22[o] = fmaf(w, h3, s22[o]);
                    s12[o] = fmaf(w, h4, s12[o]);
                }
            }
        }
        bool colok = (ox0 + j) < OW;
#pragma unroll
        for (int o = 0; o < 4; o++) {
            if (colok && (oy0 + i0 + o) < OW) {
                float mu1 = m1[o], mu2 = m2[o];
                float mu1s = mu1 * mu1;
                float mu2s = mu2 * mu2;
                float mu12 = mu1 * mu2;
                float v1 = 2.f * (s12[o] - mu12) + C2v;
                float v2 = (s11[o] - mu1s) + (s22[o] - mu2s) + C2v;
                cs_acc   += __fdividef(v1, v2);
                ssim_acc += __fdividef((2.f * mu12 + C1v) * v1,
                                       (mu1s + mu2s + C1v) * v2);
            }
        }
    }

#pragma unroll
    for (int s = 16; s > 0; s >>= 1) {
        cs_acc   += __shfl_xor_sync(0xffffffff, cs_acc, s);
        ssim_acc += __shfl_xor_sync(0xffffffff, ssim_acc, s);
    }
    int warp = tid >> 5, lane = tid & 31;
    if (lane == 0) { red_cs[warp] = cs_acc; red_ss[warp] = ssim_acc; }
    __syncthreads();
    if (tid == 0) {
        float tc = 0.f, ts = 0.f;
#pragma unroll
        for (int w = 0; w < 8; w++) { tc += red_cs[w]; ts += red_ss[w]; }
        atomicAdd(&g_cs[level][b],   (double)tc);
        atomicAdd(&g_ssim[level][b], (double)ts);
    }
}

// ---- Level-0 kernel: ssim @512 + builds ALL pyramid levels ---------------
__global__ __launch_bounds__(NTHREADS)
void ssim0_kernel(const float* __restrict__ x, const float* __restrict__ y,
                  float* __restrict__ bx_, float* __restrict__ by_) {
    __shared__ float sx[IH][SXP];
    __shared__ float sy[IH][SXP];
    __shared__ float h[5][IH][HP];
    __shared__ float red_cs[8], red_ss[8];
    __shared__ float sp2x[64], sp2y[64], sp3x[16], sp3y[16];

    const int img = blockIdx.z;
    const int b   = img / CH;
    const float* xp = x + (size_t)img * 512 * 512;
    const float* yp = y + (size_t)img * 512 * 512;

    const int bxi = blockIdx.x, byi = blockIdx.y;
    const int ox0 = bxi * TW, oy0 = byi * TH;
    const int tid = threadIdx.x;

    // Phase 1: load 38x38 window
    if (bxi < 15 && byi < 15) {
        for (int t = tid; t < 380; t += NTHREADS) {
            int r = t / 10, v = t - r * 10;
            const float* rowx = xp + (size_t)(oy0 + r) * 512 + ox0;
            const float* rowy = yp + (size_t)(oy0 + r) * 512 + ox0;
            if (v < 9) {
                float4 a = __ldg((const float4*)rowx + v);
                float4 c = __ldg((const float4*)rowy + v);
                int cc = v << 2;
                sx[r][cc] = a.x; sx[r][cc+1] = a.y; sx[r][cc+2] = a.z; sx[r][cc+3] = a.w;
                sy[r][cc] = c.x; sy[r][cc+1] = c.y; sy[r][cc+2] = c.z; sy[r][cc+3] = c.w;
            } else {
                float2 a = __ldg((const float2*)(rowx + 36));
                float2 c = __ldg((const float2*)(rowy + 36));
                sx[r][36] = a.x; sx[r][37] = a.y;
                sy[r][36] = c.x; sy[r][37] = c.y;
            }
        }
    } else {
        for (int e = tid; e < IH * IW; e += NTHREADS) {
            int r = e / IW, c = e - r * IW;
            int gy = oy0 + r, gx = ox0 + c;
            float xv = 0.f, yv = 0.f;
            if (gy < 512 && gx < 512) {
                xv = __ldg(&xp[(size_t)gy * 512 + gx]);
                yv = __ldg(&yp[(size_t)gy * 512 + gx]);
            }
            sx[r][c] = xv;
            sy[r][c] = yv;
        }
    }
    __syncthreads();

    // Pyramid build from 32x32 core region (always fully in-bounds)
    {
        int pi = tid >> 4, pj = tid & 15;
        int r = 2 * pi, c = 2 * pj;
        float pvx = 0.25f * (sx[r][c] + sx[r][c+1] + sx[r+1][c] + sx[r+1][c+1]);
        float pvy = 0.25f * (sy[r][c] + sy[r][c+1] + sy[r+1][c] + sy[r+1][c+1]);
        size_t d1 = (size_t)img * 256 * 256 + ((size_t)(oy0 >> 1) + pi) * 256 + (ox0 >> 1) + pj;
        bx_[OFF1 + d1] = pvx;
        by_[OFF1 + d1] = pvy;
        int lane = tid & 31, wid = tid >> 5;
        float s2x = pvx + __shfl_xor_sync(0xffffffff, pvx, 1);
        s2x += __shfl_xor_sync(0xffffffff, s2x, 16);
        float s2y = pvy + __shfl_xor_sync(0xffffffff, pvy, 1);
        s2y += __shfl_xor_sync(0xffffffff, s2y, 16);
        if ((lane & 17) == 0) {
            float p2x = 0.25f * s2x, p2y = 0.25f * s2y;
            int i2 = wid, j2 = lane >> 1;
            size_t d2 = (size_t)img * 128 * 128 + ((size_t)(oy0 >> 2) + i2) * 128 + (ox0 >> 2) + j2;
            bx_[OFF2 + d2] = p2x;
            by_[OFF2 + d2] = p2y;
            sp2x[i2 * 8 + j2] = p2x;
            sp2y[i2 * 8 + j2] = p2y;
        }
    }
    __syncthreads();
    if (tid < 16) {
        int i3 = tid >> 2, j3 = tid & 3;
        int r = 2 * i3, c = 2 * j3;
        float p3x = 0.25f * (sp2x[r*8+c] + sp2x[r*8+c+1] + sp2x[(r+1)*8+c] + sp2x[(r+1)*8+c+1]);
        float p3y = 0.25f * (sp2y[r*8+c] + sp2y[r*8+c+1] + sp2y[(r+1)*8+c] + sp2y[(r+1)*8+c+1]);
        size_t d3 = (size_t)img * 64 * 64 + ((size_t)(oy0 >> 3) + i3) * 64 + (ox0 >> 3) + j3;
        bx_[OFF3 + d3] = p3x;
        by_[OFF3 + d3] = p3y;
        sp3x[tid] = p3x;
        sp3y[tid] = p3y;
    }
    __syncthreads();
    if (tid < 4) {
        int i4 = tid >> 1, j4 = tid & 1;
        int r = 2 * i4, c = 2 * j4;
        float p4x = 0.25f * (sp3x[r*4+c] + sp3x[r*4+c+1] + sp3x[(r+1)*4+c] + sp3x[(r+1)*4+c+1]);
        float p4y = 0.25f * (sp3y[r*4+c] + sp3y[r*4+c+1] + sp3y[(r+1)*4+c] + sp3y[(r+1)*4+c+1]);
        size_t d4 = (size_t)img * 32 * 32 + ((size_t)(oy0 >> 4) + i4) * 32 + (ox0 >> 4) + j4;
        bx_[OFF4 + d4] = p4x;
        by_[OFF4 + d4] = p4y;
    }

    ssim_core(sx, sy, h, red_cs, red_ss, tid, ox0, oy0, 506, 0, b);
}

// ---- Batched levels 1..4 kernel ------------------------------------------
__global__ __launch_bounds__(NTHREADS)
void ssimL_kernel(const float* __restrict__ bx_, const float* __restrict__ by_) {
    const int z   = blockIdx.z;
    const int lvl = z / NIMG;          // 0..3 -> actual level 1..4
    const int img = z - lvl * NIMG;

    const int Wtab[4]  = {256, 128, 64, 32};
    const int nttab[4] = {8, 4, 2, 1};
    const size_t offtab[4] = {OFF1, OFF2, OFF3, OFF4};

    const int W  = Wtab[lvl];
    const int nt = nttab[lvl];
    if ((int)blockIdx.x >= nt || (int)blockIdx.y >= nt) return;

    __shared__ float sx[IH][SXP];
    __shared__ float sy[IH][SXP];
    __shared__ float h[5][IH][HP];
    __shared__ float red_cs[8], red_ss[8];

    const int b = img / CH;
    const float* xp = bx_ + offtab[lvl] + (size_t)img * W * W;
    const float* yp = by_ + offtab[lvl] + (size_t)img * W * W;

    const int ox0 = blockIdx.x * TW;
    const int oy0 = blockIdx.y * TH;
    const int tid = threadIdx.x;

    if (ox0 + IW <= W && oy0 + IW <= W) {
        for (int t = tid; t < 380; t += NTHREADS) {
            int r = t / 10, v = t - r * 10;
            const float* rowx = xp + (size_t)(oy0 + r) * W + ox0;
            const float* rowy = yp + (size_t)(oy0 + r) * W + ox0;
            if (v < 9) {
                float4 a = __ldg((const float4*)rowx + v);
                float4 c = __ldg((const float4*)rowy + v);
                int cc = v << 2;
                sx[r][cc] = a.x; sx[r][cc+1] = a.y; sx[r][cc+2] = a.z; sx[r][cc+3] = a.w;
                sy[r][cc] = c.x; sy[r][cc+1] = c.y; sy[r][cc+2] = c.z; sy[r][cc+3] = c.w;
            } else {
                float2 a = __ldg((const float2*)(rowx + 36));
                float2 c = __ldg((const float2*)(rowy + 36));
                sx[r][36] = a.x; sx[r][37] = a.y;
                sy[r][36] = c.x; sy[r][37] = c.y;
            }
        }
    } else {
        for (int e = tid; e < IH * IW; e += NTHREADS) {
            int r = e / IW, c = e - r * IW;
            int gy = oy0 + r, gx = ox0 + c;
            float xv = 0.f, yv = 0.f;
            if (gy < W && gx < W) {
                xv = __ldg(&xp[(size_t)gy * W + gx]);
                yv = __ldg(&yp[(size_t)gy * W + gx]);
            }
            sx[r][c] = xv;
            sy[r][c] = yv;
        }
    }
    __syncthreads();

    ssim_core(sx, sy, h, red_cs, red_ss, tid, ox0, oy0, W - 6, 1 + lvl, b);
}

// ---- Parallel epilogue: one warp, fp32 log/exp geometric mean ------------
__global__ void final_kernel(float* out) {
    const int t = threadIdx.x;
    float m = 0.f;
    if (t < B) {
        const float wts[5] = {0.0448f, 0.2856f, 0.3001f, 0.2363f, 0.1333f};
        const float inv_cnt[5] = {
            1.f / (CH * 506.f * 506.f), 1.f / (CH * 250.f * 250.f),
            1.f / (CH * 122.f * 122.f), 1.f / (CH * 58.f * 58.f),
            1.f / (CH * 26.f * 26.f)
        };
        float vals[5];
        vals[0] = (float)g_ssim[4][t] * inv_cnt[4];
        vals[1] = (float)g_cs[0][t]   * inv_cnt[0];
        vals[2] = (float)g_cs[1][t]   * inv_cnt[1];
        vals[3] = (float)g_cs[2][t]   * inv_cnt[2];
        vals[4] = (float)g_cs[3][t]   * inv_cnt[3];
        float lacc = 0.f;
#pragma unroll
        for (int l = 0; l < 5; l++) {
            float v = vals[l] < 1e-6f ? 1e-6f : vals[l];
            lacc = fmaf(wts[l], __logf(v), lacc);
        }
        m = __expf(lacc);
    }
#pragma unroll
    for (int s = 8; s > 0; s >>= 1)
        m += __shfl_xor_sync(0xffffffff, m, s);
    if (t == 0)
        out[0] = 1.f - m * (1.f / (float)B);
}

extern "C" void kernel_launch(void* const* d_in, const int* in_sizes, int n_in,
                              void* d_out, int out_size) {
    const float* x0 = (const float*)d_in[0];
    const float* y0 = (const float*)d_in[1];
    float* out = (float*)d_out;

    float *bx, *by;
    cudaGetSymbolAddress((void**)&bx, g_bufx);
    cudaGetSymbolAddress((void**)&by, g_bufy);

    zero_acc_kernel<<<1, 256>>>();

    dim3 g0(16, 16, NIMG);
    ssim0_kernel<<<g0, NTHREADS>>>(x0, y0, bx, by);

    dim3 gL(8, 8, 4 * NIMG);
    ssimL_kernel<<<gL, NTHREADS>>>(bx, by);

    final_kernel<<<1, 32>>>(out);
}

// round 7
// speedup vs baseline: 1.9836x; 1.0804x over previous
#include <cuda_runtime.h>
#include <cuda_bf16.h>

// ---------------------------------------------------------------------------
// MS-SSIM loss, (16,3,512,512) fp32, 5 levels, 7x7 Gaussian.
// R6: packed f32x2 conv math (fma.rn.f32x2): (mu1,mu2) and (sxx,syy) as
// packed lanes, interleaved float2 smem (LDS.64), packed h stats,
// immediate-constant weights. ~35% fewer issue slots per output.
// ---------------------------------------------------------------------------

typedef unsigned long long u64;

#define B      16
#define CH     3
#define NIMG   (B * CH)

#define TW 32
#define TH 32
#define IW 38
#define IH 38
#define SXP2 39     // sxy row stride in u64 (odd -> conflict-free)
#define HP  33      // h row stride (odd)
#define NTHREADS 256

// Gaussian weights as compile-time literals (FFMA-imm, no LDC)
#define G0_ 0.036632845f
#define G1_ 0.111280762f
#define G2_ 0.216745317f
#define G3_ 0.270682752f

#define C1v 0.0001f
#define C2v 0.0009f

// ---- f32x2 packed helpers -------------------------------------------------
__device__ __forceinline__ u64 fma2(u64 a, u64 b, u64 c) {
    u64 d; asm("fma.rn.f32x2 %0, %1, %2, %3;" : "=l"(d) : "l"(a), "l"(b), "l"(c));
    return d;
}
__device__ __forceinline__ u64 mul2(u64 a, u64 b) {
    u64 d; asm("mul.rn.f32x2 %0, %1, %2;" : "=l"(d) : "l"(a), "l"(b));
    return d;
}
__device__ __forceinline__ u64 pk2(float lo, float hi) {
    u64 r; asm("mov.b64 %0, {%1, %2};" : "=l"(r) : "f"(lo), "f"(hi));
    return r;
}
__device__ __forceinline__ void upk2(u64 v, float& lo, float& hi) {
    asm("mov.b64 {%0, %1}, %2;" : "=f"(lo), "=f"(hi) : "l"(v));
}

__device__ double g_cs[5][B];
__device__ double g_ssim[5][B];

// Pyramid scratch (levels 1..4), x and y
#define OFF1 0
#define OFF2 (NIMG * 256 * 256)
#define OFF3 (OFF2 + NIMG * 128 * 128)
#define OFF4 (OFF3 + NIMG * 64 * 64)
#define BUFTOT (OFF4 + NIMG * 32 * 32)
__device__ float g_bufx[BUFTOT];
__device__ float g_bufy[BUFTOT];

__global__ void zero_acc_kernel() {
    int t = threadIdx.x;
    double* cs = &g_cs[0][0];
    double* ss = &g_ssim[0][0];
    if (t < 5 * B)        cs[t] = 0.0;
    else if (t < 10 * B)  ss[t - 5 * B] = 0.0;
}

// ---- shared phase 2+3+reduce body (sxy already in smem) -------------------
__device__ __forceinline__ void ssim_core(
    u64 (*sxy)[SXP2], u64 (*h01)[HP], u64 (*h23)[HP], float (*h4)[HP],
    float* red_cs, float* red_ss,
    int tid, int ox0, int oy0, int OW, int level, int b) {

    constexpr float Gc[7] = {G0_, G1_, G2_, G3_, G2_, G1_, G0_};
    u64 W2[7];
#pragma unroll
    for (int k = 0; k < 7; k++) W2[k] = pk2(Gc[k], Gc[k]);

    // Phase 2: horizontal Gaussian, 4 cols per task, packed channels
    for (int t = tid; t < IH * 8; t += NTHREADS) {
        int r  = t >> 3;
        int c0 = (t & 7) << 2;
        u64 A01[4] = {0,0,0,0};     // packed (mu1, mu2)
        u64 A23[4] = {0,0,0,0};     // packed (E[xx], E[yy])
        float A4[4] = {0,0,0,0};    // E[xy]
#pragma unroll
        for (int e = 0; e < 10; e++) {
            u64 xy = sxy[r][c0 + e];
            u64 sq = mul2(xy, xy);
            float xv, yv; upk2(xy, xv, yv);
            float xyv = xv * yv;
#pragma unroll
            for (int o = 0; o < 4; o++) {
                int k = e - o;
                if (k >= 0 && k < 7) {
                    A01[o] = fma2(xy, W2[k], A01[o]);
                    A23[o] = fma2(sq, W2[k], A23[o]);
                    A4[o]  = fmaf(xyv, Gc[k], A4[o]);
                }
            }
        }
#pragma unroll
        for (int o = 0; o < 4; o++) {
            h01[r][c0 + o] = A01[o];
            h23[r][c0 + o] = A23[o];
            h4[r][c0 + o]  = A4[o];
        }
    }
    __syncthreads();

    // Phase 3: vertical Gaussian, 4 rows per thread, packed channels
    float cs_acc = 0.f, ssim_acc = 0.f;
    {
        int j  = tid & 31;
        int i0 = (tid >> 5) << 2;
        u64 M[4] = {0,0,0,0};       // packed (mu1, mu2)
        u64 S[4] = {0,0,0,0};       // packed (sxx, syy)
        float S12[4] = {0,0,0,0};
#pragma unroll
        for (int k = 0; k < 10; k++) {
            u64 a  = h01[i0 + k][j];
            u64 bb = h23[i0 + k][j];
            float c4 = h4[i0 + k][j];
#pragma unroll
            for (int o = 0; o < 4; o++) {
                int kk = k - o;
                if (kk >= 0 && kk < 7) {
                    M[o]   = fma2(a,  W2[kk], M[o]);
                    S[o]   = fma2(bb, W2[kk], S[o]);
                    S12[o] = fmaf(c4, Gc[kk], S12[o]);
                }
            }
        }
        bool colok = (ox0 + j) < OW;
#pragma unroll
        for (int o = 0; o < 4; o++) {
            if (colok && (oy0 + i0 + o) < OW) {
                float mu1, mu2; upk2(M[o], mu1, mu2);
                float sxx, syy; upk2(S[o], sxx, syy);
                float mu1s = mu1 * mu1;
                float mu2s = mu2 * mu2;
                float mu12 = mu1 * mu2;
                float v1 = 2.f * (S12[o] - mu12) + C2v;
                float v2 = (sxx - mu1s) + (syy - mu2s) + C2v;
                cs_acc   += __fdividef(v1, v2);
                ssim_acc += __fdividef((2.f * mu12 + C1v) * v1,
                                       (mu1s + mu2s + C1v) * v2);
            }
        }
    }

#pragma unroll
    for (int s = 16; s > 0; s >>= 1) {
        cs_acc   += __shfl_xor_sync(0xffffffff, cs_acc, s);
        ssim_acc += __shfl_xor_sync(0xffffffff, ssim_acc, s);
    }
    int warp = tid >> 5, lane = tid & 31;
    if (lane == 0) { red_cs[warp] = cs_acc; red_ss[warp] = ssim_acc; }
    __syncthreads();
    if (tid == 0) {
        float tc = 0.f, ts = 0.f;
#pragma unroll
        for (int w = 0; w < 8; w++) { tc += red_cs[w]; ts += red_ss[w]; }
        atomicAdd(&g_cs[level][b],   (double)tc);
        atomicAdd(&g_ssim[level][b], (double)ts);
    }
}

// ---- Level-0 kernel: ssim @512 + builds ALL pyramid levels ---------------
__global__ __launch_bounds__(NTHREADS)
void ssim0_kernel(const float* __restrict__ x, const float* __restrict__ y,
                  float* __restrict__ bx_, float* __restrict__ by_) {
    __shared__ u64   sxy[IH][SXP2];
    __shared__ u64   h01[IH][HP];
    __shared__ u64   h23[IH][HP];
    __shared__ float h4[IH][HP];
    __shared__ float red_cs[8], red_ss[8];
    __shared__ float sp2x[64], sp2y[64], sp3x[16], sp3y[16];

    const int img = blockIdx.z;
    const int b   = img / CH;
    const float* xp = x + (size_t)img * 512 * 512;
    const float* yp = y + (size_t)img * 512 * 512;

    const int bxi = blockIdx.x, byi = blockIdx.y;
    const int ox0 = bxi * TW, oy0 = byi * TH;
    const int tid = threadIdx.x;

    // Phase 1: load 38x38 window, interleave (x,y) pairs
    if (bxi < 15 && byi < 15) {
        for (int t = tid; t < 380; t += NTHREADS) {
            int r = t / 10, v = t - r * 10;
            const float* rowx = xp + (size_t)(oy0 + r) * 512 + ox0;
            const float* rowy = yp + (size_t)(oy0 + r) * 512 + ox0;
            if (v < 9) {
                float4 a = __ldg((const float4*)rowx + v);
                float4 c = __ldg((const float4*)rowy + v);
                int cc = v << 2;
                sxy[r][cc]   = pk2(a.x, c.x);
                sxy[r][cc+1] = pk2(a.y, c.y);
                sxy[r][cc+2] = pk2(a.z, c.z);
                sxy[r][cc+3] = pk2(a.w, c.w);
            } else {
                float2 a = __ldg((const float2*)(rowx + 36));
                float2 c = __ldg((const float2*)(rowy + 36));
                sxy[r][36] = pk2(a.x, c.x);
                sxy[r][37] = pk2(a.y, c.y);
            }
        }
    } else {
        for (int e = tid; e < IH * IW; e += NTHREADS) {
            int r = e / IW, c = e - r * IW;
            int gy = oy0 + r, gx = ox0 + c;
            float xv = 0.f, yv = 0.f;
            if (gy < 512 && gx < 512) {
                xv = __ldg(&xp[(size_t)gy * 512 + gx]);
                yv = __ldg(&yp[(size_t)gy * 512 + gx]);
            }
            sxy[r][c] = pk2(xv, yv);
        }
    }
    __syncthreads();

    // Pyramid build from 32x32 core region (always fully in-bounds)
    {
        int pi = tid >> 4, pj = tid & 15;
        int r = 2 * pi, c = 2 * pj;
        float x00, y00, x01, y01, x10, y10, x11, y11;
        upk2(sxy[r][c],     x00, y00);
        upk2(sxy[r][c+1],   x01, y01);
        upk2(sxy[r+1][c],   x10, y10);
        upk2(sxy[r+1][c+1], x11, y11);
        float pvx = 0.25f * (x00 + x01 + x10 + x11);
        float pvy = 0.25f * (y00 + y01 + y10 + y11);
        size_t d1 = (size_t)img * 256 * 256 + ((size_t)(oy0 >> 1) + pi) * 256 + (ox0 >> 1) + pj;
        bx_[OFF1 + d1] = pvx;
        by_[OFF1 + d1] = pvy;
        int lane = tid & 31, wid = tid >> 5;
        float s2x = pvx + __shfl_xor_sync(0xffffffff, pvx, 1);
        s2x += __shfl_xor_sync(0xffffffff, s2x, 16);
        float s2y = pvy + __shfl_xor_sync(0xffffffff, pvy, 1);
        s2y += __shfl_xor_sync(0xffffffff, s2y, 16);
        if ((lane & 17) == 0) {
            float p2x = 0.25f * s2x, p2y = 0.25f * s2y;
            int i2 = wid, j2 = lane >> 1;
            size_t d2 = (size_t)img * 128 * 128 + ((size_t)(oy0 >> 2) + i2) * 128 + (ox0 >> 2) + j2;
            bx_[OFF2 + d2] = p2x;
            by_[OFF2 + d2] = p2y;
            sp2x[i2 * 8 + j2] = p2x;
            sp2y[i2 * 8 + j2] = p2y;
        }
    }
    __syncthreads();
    if (tid < 16) {
        int i3 = tid >> 2, j3 = tid & 3;
        int r = 2 * i3, c = 2 * j3;
        float p3x = 0.25f * (sp2x[r*8+c] + sp2x[r*8+c+1] + sp2x[(r+1)*8+c] + sp2x[(r+1)*8+c+1]);
        float p3y = 0.25f * (sp2y[r*8+c] + sp2y[r*8+c+1] + sp2y[(r+1)*8+c] + sp2y[(r+1)*8+c+1]);
        size_t d3 = (size_t)img * 64 * 64 + ((size_t)(oy0 >> 3) + i3) * 64 + (ox0 >> 3) + j3;
        bx_[OFF3 + d3] = p3x;
        by_[OFF3 + d3] = p3y;
        sp3x[tid] = p3x;
        sp3y[tid] = p3y;
    }
    __syncthreads();
    if (tid < 4) {
        int i4 = tid >> 1, j4 = tid & 1;
        int r = 2 * i4, c = 2 * j4;
        float p4x = 0.25f * (sp3x[r*4+c] + sp3x[r*4+c+1] + sp3x[(r+1)*4+c] + sp3x[(r+1)*4+c+1]);
        float p4y = 0.25f * (sp3y[r*4+c] + sp3y[r*4+c+1] + sp3y[(r+1)*4+c] + sp3y[(r+1)*4+c+1]);
        size_t d4 = (size_t)img * 32 * 32 + ((size_t)(oy0 >> 4) + i4) * 32 + (ox0 >> 4) + j4;
        bx_[OFF4 + d4] = p4x;
        by_[OFF4 + d4] = p4y;
    }

    ssim_core(sxy, h01, h23, h4, red_cs, red_ss, tid, ox0, oy0, 506, 0, b);
}

// ---- Batched levels 1..4 kernel ------------------------------------------
__global__ __launch_bounds__(NTHREADS)
void ssimL_kernel(const float* __restrict__ bx_, const float* __restrict__ by_) {
    const int z   = blockIdx.z;
    const int lvl = z / NIMG;          // 0..3 -> actual level 1..4
    const int img = z - lvl * NIMG;

    const int Wtab[4]  = {256, 128, 64, 32};
    const int nttab[4] = {8, 4, 2, 1};
    const size_t offtab[4] = {OFF1, OFF2, OFF3, OFF4};

    const int W  = Wtab[lvl];
    const int nt = nttab[lvl];
    if ((int)blockIdx.x >= nt || (int)blockIdx.y >= nt) return;

    __shared__ u64   sxy[IH][SXP2];
    __shared__ u64   h01[IH][HP];
    __shared__ u64   h23[IH][HP];
    __shared__ float h4[IH][HP];
    __shared__ float red_cs[8], red_ss[8];

    const int b = img / CH;
    const float* xp = bx_ + offtab[lvl] + (size_t)img * W * W;
    const float* yp = by_ + offtab[lvl] + (size_t)img * W * W;

    const int ox0 = blockIdx.x * TW;
    const int oy0 = blockIdx.y * TH;
    const int tid = threadIdx.x;

    if (ox0 + IW <= W && oy0 + IW <= W) {
        for (int t = tid; t < 380; t += NTHREADS) {
            int r = t / 10, v = t - r * 10;
            const float* rowx = xp + (size_t)(oy0 + r) * W + ox0;
            const float* rowy = yp + (size_t)(oy0 + r) * W + ox0;
            if (v < 9) {
                float4 a = __ldg((const float4*)rowx + v);
                float4 c = __ldg((const float4*)rowy + v);
                int cc = v << 2;
                sxy[r][cc]   = pk2(a.x, c.x);
                sxy[r][cc+1] = pk2(a.y, c.y);
                sxy[r][cc+2] = pk2(a.z, c.z);
                sxy[r][cc+3] = pk2(a.w, c.w);
            } else {
                float2 a = __ldg((const float2*)(rowx + 36));
                float2 c = __ldg((const float2*)(rowy + 36));
                sxy[r][36] = pk2(a.x, c.x);
                sxy[r][37] = pk2(a.y, c.y);
            }
        }
    } else {
        for (int e = tid; e < IH * IW; e += NTHREADS) {
            int r = e / IW, c = e - r * IW;
            int gy = oy0 + r, gx = ox0 + c;
            float xv = 0.f, yv = 0.f;
            if (gy < W && gx < W) {
                xv = __ldg(&xp[(size_t)gy * W + gx]);
                yv = __ldg(&yp[(size_t)gy * W + gx]);
            }
            sxy[r][c] = pk2(xv, yv);
        }
    }
    __syncthreads();

    ssim_core(sxy, h01, h23, h4, red_cs, red_ss, tid, ox0, oy0, W - 6, 1 + lvl, b);
}

// ---- Parallel epilogue: one warp, fp32 log/exp geometric mean ------------
__global__ void final_kernel(float* out) {
    const int t = threadIdx.x;
    float m = 0.f;
    if (t < B) {
        const float wts[5] = {0.0448f, 0.2856f, 0.3001f, 0.2363f, 0.1333f};
        const float inv_cnt[5] = {
            1.f / (CH * 506.f * 506.f), 1.f / (CH * 250.f * 250.f),
            1.f / (CH * 122.f * 122.f), 1.f / (CH * 58.f * 58.f),
            1.f / (CH * 26.f * 26.f)
        };
        float vals[5];
        vals[0] = (float)g_ssim[4][t] * inv_cnt[4];
        vals[1] = (float)g_cs[0][t]   * inv_cnt[0];
        vals[2] = (float)g_cs[1][t]   * inv_cnt[1];
        vals[3] = (float)g_cs[2][t]   * inv_cnt[2];
        vals[4] = (float)g_cs[3][t]   * inv_cnt[3];
        float lacc = 0.f;
#pragma unroll
        for (int l = 0; l < 5; l++) {
            float v = vals[l] < 1e-6f ? 1e-6f : vals[l];
            lacc = fmaf(wts[l], __logf(v), lacc);
        }
        m = __expf(lacc);
    }
#pragma unroll
    for (int s = 8; s > 0; s >>= 1)
        m += __shfl_xor_sync(0xffffffff, m, s);
    if (t == 0)
        out[0] = 1.f - m * (1.f / (float)B);
}

extern "C" void kernel_launch(void* const* d_in, const int* in_sizes, int n_in,
                              void* d_out, int out_size) {
    const float* x0 = (const float*)d_in[0];
    const float* y0 = (const float*)d_in[1];
    float* out = (float*)d_out;

    float *bx, *by;
    cudaGetSymbolAddress((void**)&bx, g_bufx);
    cudaGetSymbolAddress((void**)&by, g_bufy);

    zero_acc_kernel<<<1, 256>>>();

    dim3 g0(16, 16, NIMG);
    ssim0_kernel<<<g0, NTHREADS>>>(x0, y0, bx, by);

    dim3 gL(8, 8, 4 * NIMG);
    ssimL_kernel<<<gL, NTHREADS>>>(bx, by);

    final_kernel<<<1, 32>>>(out);
}